// round 15
// baseline (speedup 1.0000x reference)
#include <cuda_runtime.h>
#include <math.h>
#include <stdint.h>

#define LSEQ   1024
#define DMODEL 4096
#define NH     32
#define QLORA  1536
#define KVLORA 512
#define ROPED  64
#define NOPED  128
#define VD     128
#define QHD    192
#define IHN    64
#define IHDN   128
#define NTOPK  256

#define ATT_SCALE 0.07216878364870323f   /* 192^-0.5 */
#define IW_SCALE  0.011048543456039806f  /* (64*128)^-0.5 */

__device__ __forceinline__ uint32_t tf32bits(float x)
{
    uint32_t u;
    asm("cvt.rna.tf32.f32 %0, %1;" : "=r"(u) : "f"(x));
    return u;
}

#define MMA8(d, a, b) \
    asm volatile( \
        "mma.sync.aligned.m16n8k8.row.col.f32.tf32.tf32.f32 " \
        "{%0,%1,%2,%3}, {%4,%5,%6,%7}, {%8,%9}, {%0,%1,%2,%3};\n" \
        : "+f"((d)[0]), "+f"((d)[1]), "+f"((d)[2]), "+f"((d)[3]) \
        : "r"((a)[0]), "r"((a)[1]), "r"((a)[2]), "r"((a)[3]), \
          "r"((b)[0]), "r"((b)[1]))

/* Correctly-rounded rope trig: replicate JAX's f32 angle, then exact sincos. */
__device__ __forceinline__ void rope_trig(int l, int i, float* sn, float* cs)
{
    double invd = pow(10000.0, -(double)i * (1.0 / 32.0));
    float  invf = (float)invd;
    float  ang  = (float)l * invf;
    double a    = (double)ang;
    *cs = (float)cos(a);
    *sn = (float)sin(a);
}

/* ---------------- scratch (device globals; no allocs allowed) ------------ */
__device__ float  g_qr   [LSEQ * QLORA];
__device__ float  g_q    [LSEQ * NH * QHD];
__device__ float  g_ckv  [LSEQ * (KVLORA + ROPED)];
__device__ float  g_kvlat[LSEQ * KVLORA];
__device__ float  g_kpe  [LSEQ * ROPED];
__device__ float  g_iq   [LSEQ * IHN * IHDN];
__device__ float  g_ik   [LSEQ * IHDN];
__device__ float  g_iw   [LSEQ * IHN];
__device__ int    g_topk [LSEQ * NTOPK];
__device__ float  g_k    [NH * LSEQ * NOPED];
__device__ float  g_ctx  [NH * LSEQ * KVLORA];   /* absorbed attention context */
__device__ float  g_ao   [LSEQ * NH * VD];
__device__ float2 g_rope [LSEQ * 32];
/* separate partial buffers for concurrent producers */
__device__ float  g_partA[2 * LSEQ * QLORA];   /* W_qa K-split partials */
__device__ float  g_partB[8 * LSEQ * IHDN];    /* idx_wk partials */
__device__ float  g_partC[8 * LSEQ * IHN];     /* idx_wproj partials */
__device__ float  g_partD[2 * LSEQ * LSEQ];    /* indexer head-group partials */

/* ================== TF32 tensor-core GEMM (proven R6/R7 version) ========= */
/* Generalized with strideA (batched A) and ldc (C row stride).             */
#define TCPAD 4
template <bool TB>
__global__ void __launch_bounds__(256)
gemm_tc(const float* __restrict__ A, const float* __restrict__ B,
        float* __restrict__ C, int M, int N, int K,
        long strideA, long strideB, long strideC, int ldc, int m0)
{
    __shared__ uint32_t As[128][32 + TCPAD];
    __shared__ uint32_t Bs[128][32 + TCPAD];

    const float* Ap = A + (long)blockIdx.z * strideA;
    const float* Bp = B + (long)blockIdx.z * strideB;
    float*       Cp = C + (long)blockIdx.z * strideC;

    const int bm   = m0 + blockIdx.y * 128;
    const int bn   = blockIdx.x * 128;
    const int tid  = threadIdx.x;
    const int wid  = tid >> 5;
    const int lane = tid & 31;
    const int g    = lane >> 2;
    const int t4   = lane & 3;

    const int wm = (wid & 1) * 64;
    const int wn = (wid >> 1) * 32;

    float acc[4][4][4];
#pragma unroll
    for (int mi = 0; mi < 4; mi++)
#pragma unroll
        for (int ni = 0; ni < 4; ni++)
#pragma unroll
            for (int r = 0; r < 4; r++) acc[mi][ni][r] = 0.f;

    const int lr = tid >> 1;
    const int lc = (tid & 1) * 16;

    for (int k0 = 0; k0 < K; k0 += 32) {
#pragma unroll
        for (int q = 0; q < 4; q++) {
            float4 v = *(const float4*)(Ap + (long)(bm + lr) * K + k0 + lc + q * 4);
            *(uint4*)&As[lr][lc + q * 4] =
                make_uint4(tf32bits(v.x), tf32bits(v.y), tf32bits(v.z), tf32bits(v.w));
        }
        if (TB) {
            int row = bn + lr;
            if (row < N) {
#pragma unroll
                for (int q = 0; q < 4; q++) {
                    float4 v = *(const float4*)(Bp + (long)row * K + k0 + lc + q * 4);
                    *(uint4*)&Bs[lr][lc + q * 4] =
                        make_uint4(tf32bits(v.x), tf32bits(v.y), tf32bits(v.z), tf32bits(v.w));
                }
            } else {
#pragma unroll
                for (int q = 0; q < 4; q++)
                    *(uint4*)&Bs[lr][lc + q * 4] = make_uint4(0, 0, 0, 0);
            }
        } else {
            int k  = tid >> 3;
            int nb = (tid & 7) * 16;
#pragma unroll
            for (int q = 0; q < 16; q += 4) {
                int n = bn + nb + q;
                if (n + 3 < N) {
                    float4 v = *(const float4*)(Bp + (long)(k0 + k) * N + n);
                    Bs[nb + q + 0][k] = tf32bits(v.x);
                    Bs[nb + q + 1][k] = tf32bits(v.y);
                    Bs[nb + q + 2][k] = tf32bits(v.z);
                    Bs[nb + q + 3][k] = tf32bits(v.w);
                } else {
#pragma unroll
                    for (int e = 0; e < 4; e++) {
                        float f = (n + e < N) ? Bp[(long)(k0 + k) * N + n + e] : 0.f;
                        Bs[nb + q + e][k] = tf32bits(f);
                    }
                }
            }
        }
        __syncthreads();

#pragma unroll
        for (int ks = 0; ks < 4; ks++) {
            const int kb = ks * 8;
            uint32_t af[4][4];
#pragma unroll
            for (int mi = 0; mi < 4; mi++) {
                int r = wm + mi * 16;
                af[mi][0] = As[r + g][kb + t4];
                af[mi][1] = As[r + g + 8][kb + t4];
                af[mi][2] = As[r + g][kb + t4 + 4];
                af[mi][3] = As[r + g + 8][kb + t4 + 4];
            }
            uint32_t bf[4][2];
#pragma unroll
            for (int ni = 0; ni < 4; ni++) {
                int c = wn + ni * 8;
                bf[ni][0] = Bs[c + g][kb + t4];
                bf[ni][1] = Bs[c + g][kb + t4 + 4];
            }
#pragma unroll
            for (int mi = 0; mi < 4; mi++)
#pragma unroll
                for (int ni = 0; ni < 4; ni++)
                    MMA8(acc[mi][ni], af[mi], bf[ni]);
        }
        __syncthreads();
    }

#pragma unroll
    for (int mi = 0; mi < 4; mi++) {
#pragma unroll
        for (int ni = 0; ni < 4; ni++) {
            int r0 = bm + wm + mi * 16 + g;
            int c0 = bn + wn + ni * 8 + t4 * 2;
            if (c0 < N) {
                Cp[(long)r0 * ldc + c0] = acc[mi][ni][0];
                if (c0 + 1 < N) Cp[(long)r0 * ldc + c0 + 1] = acc[mi][ni][1];
                Cp[(long)(r0 + 8) * ldc + c0] = acc[mi][ni][2];
                if (c0 + 1 < N) Cp[(long)(r0 + 8) * ldc + c0 + 1] = acc[mi][ni][3];
            }
        }
    }
}

/* ============ Kahan fp32 GEMM (score path, exact class), K-split ========= */
template <int SPLIT>
__global__ void __launch_bounds__(256)
gemm_k128(const float* __restrict__ A, const float* __restrict__ B,
          float* __restrict__ C, int M, int N, int K, int m0)
{
    __shared__ float As[16][128];
    __shared__ float Bs[16][64];

    const int bm    = m0 + blockIdx.y * 128;
    const int bn    = blockIdx.x * 64;
    const int kLen  = K / SPLIT;
    const int kBase = blockIdx.z * kLen;
    float* Cp = C + (long)blockIdx.z * M * N;

    const int tid = threadIdx.x;
    const int tm  = tid >> 4;
    const int tn  = tid & 15;

    const int ar = tid >> 1;
    const int ac = (tid & 1) << 3;
    const int br = tid >> 2;
    const int bc = (tid & 3) << 2;

    float s_[8][4], c_[8][4];
#pragma unroll
    for (int i = 0; i < 8; i++)
#pragma unroll
        for (int j = 0; j < 4; j++) { s_[i][j] = 0.f; c_[i][j] = 0.f; }

    for (int k0 = kBase; k0 < kBase + kLen; k0 += 16) {
        float4 a0 = *(const float4*)(A + (long)(bm + ar) * K + k0 + ac);
        float4 a1 = *(const float4*)(A + (long)(bm + ar) * K + k0 + ac + 4);
        As[ac + 0][ar] = a0.x; As[ac + 1][ar] = a0.y;
        As[ac + 2][ar] = a0.z; As[ac + 3][ar] = a0.w;
        As[ac + 4][ar] = a1.x; As[ac + 5][ar] = a1.y;
        As[ac + 6][ar] = a1.z; As[ac + 7][ar] = a1.w;

        float4 b0 = *(const float4*)(B + (long)(bn + br) * K + k0 + bc);
        Bs[bc + 0][br] = b0.x; Bs[bc + 1][br] = b0.y;
        Bs[bc + 2][br] = b0.z; Bs[bc + 3][br] = b0.w;
        __syncthreads();

        float t_[8][4];
#pragma unroll
        for (int i = 0; i < 8; i++)
#pragma unroll
            for (int j = 0; j < 4; j++) t_[i][j] = 0.f;

#pragma unroll
        for (int kk = 0; kk < 16; kk++) {
            float4 va0 = *(const float4*)&As[kk][tm << 3];
            float4 va1 = *(const float4*)&As[kk][(tm << 3) + 4];
            float4 vb  = *(const float4*)&Bs[kk][tn << 2];
            float av[8] = {va0.x, va0.y, va0.z, va0.w, va1.x, va1.y, va1.z, va1.w};
            float bv[4] = {vb.x, vb.y, vb.z, vb.w};
#pragma unroll
            for (int i = 0; i < 8; i++)
#pragma unroll
                for (int j = 0; j < 4; j++)
                    t_[i][j] = __fmaf_rn(av[i], bv[j], t_[i][j]);
        }
#pragma unroll
        for (int i = 0; i < 8; i++)
#pragma unroll
            for (int j = 0; j < 4; j++) {
                float y = __fsub_rn(t_[i][j], c_[i][j]);
                float u = __fadd_rn(s_[i][j], y);
                c_[i][j] = __fsub_rn(__fsub_rn(u, s_[i][j]), y);
                s_[i][j] = u;
            }
        __syncthreads();
    }

#pragma unroll
    for (int i = 0; i < 8; i++) {
        float4 r;
        r.x = s_[i][0]; r.y = s_[i][1]; r.z = s_[i][2]; r.w = s_[i][3];
        *(float4*)(Cp + (long)(bm + (tm << 3) + i) * N + bn + (tn << 2)) = r;
    }
}

/* ---------------- combine K-split partials (strided planes) ------------- */
__global__ void combine_kernel(const float* __restrict__ part,
                               float* __restrict__ dst, int count, int S,
                               long stride)
{
    int i = blockIdx.x * 256 + threadIdx.x;
    if (i < count) {
        float s = part[i];
        for (int k = 1; k < S; k++) s = __fadd_rn(s, part[(long)k * stride + i]);
        dst[i] = s;
    }
}

/* ---------------- rmsnorm over a row (double-precision stats) ---------- */
__global__ void rmsnorm_kernel(const float* __restrict__ in,
                               const float* __restrict__ w,
                               float* __restrict__ out,
                               int cols, int inStride, int outStride, float eps)
{
    const int l = blockIdx.x;
    const int t = threadIdx.x;
    __shared__ double red[8];
    __shared__ float rshared;

    double ss = 0.0;
    for (int c = t; c < cols; c += 256) {
        double v = (double)in[(long)l * inStride + c];
        ss += v * v;
    }
#pragma unroll
    for (int o = 16; o; o >>= 1) ss += __shfl_xor_sync(0xffffffffu, ss, o);
    if ((t & 31) == 0) red[t >> 5] = ss;
    __syncthreads();
    if (t == 0) {
        double s = 0.0;
        for (int i = 0; i < 8; i++) s += red[i];
        rshared = (float)rsqrt(s / (double)cols + (double)eps);
    }
    __syncthreads();
    float r = rshared;
    for (int c = t; c < cols; c += 256)
        out[(long)l * outStride + c] = in[(long)l * inStride + c] * r * w[c];
}

/* ------ rmsnorm reading 2 K-split planes (bit-exact combine fold) ------ */
__global__ void rmsnorm_sum2_kernel(const float* __restrict__ part, long plane,
                                    const float* __restrict__ w,
                                    float* __restrict__ out,
                                    int cols, float eps)
{
    const int l = blockIdx.x;
    const int t = threadIdx.x;
    __shared__ double red[8];
    __shared__ float rshared;

    double ss = 0.0;
    for (int c = t; c < cols; c += 256) {
        float v = __fadd_rn(part[(long)l * cols + c], part[plane + (long)l * cols + c]);
        double dv = (double)v;
        ss += dv * dv;
    }
#pragma unroll
    for (int o = 16; o; o >>= 1) ss += __shfl_xor_sync(0xffffffffu, ss, o);
    if ((t & 31) == 0) red[t >> 5] = ss;
    __syncthreads();
    if (t == 0) {
        double s = 0.0;
        for (int i = 0; i < 8; i++) s += red[i];
        rshared = (float)rsqrt(s / (double)cols + (double)eps);
    }
    __syncthreads();
    float r = rshared;
    for (int c = t; c < cols; c += 256) {
        float v = __fadd_rn(part[(long)l * cols + c], part[plane + (long)l * cols + c]);
        out[(long)l * cols + c] = v * r * w[c];
    }
}

/* -------- layernorm on summed idx_wk planes -> g_ik (combine fold) ----- */
__global__ void layernorm_ik_kernel(const float* __restrict__ part, long plane,
                                    const float* __restrict__ w,
                                    const float* __restrict__ b)
{
    const int l = blockIdx.x;
    const int t = threadIdx.x;
    __shared__ double red[4];
    __shared__ double stat;

    float v = part[(long)l * IHDN + t];
#pragma unroll
    for (int k = 1; k < 8; k++)
        v = __fadd_rn(v, part[(long)k * plane + (long)l * IHDN + t]);

    double s = (double)v;
#pragma unroll
    for (int o = 16; o; o >>= 1) s += __shfl_xor_sync(0xffffffffu, s, o);
    if ((t & 31) == 0) red[t >> 5] = s;
    __syncthreads();
    if (t == 0) stat = (red[0] + red[1] + red[2] + red[3]) * (1.0 / 128.0);
    __syncthreads();
    double mu = stat;
    double d  = (double)v - mu;

    double s2 = d * d;
#pragma unroll
    for (int o = 16; o; o >>= 1) s2 += __shfl_xor_sync(0xffffffffu, s2, o);
    __syncthreads();
    if ((t & 31) == 0) red[t >> 5] = s2;
    __syncthreads();
    if (t == 0) stat = (red[0] + red[1] + red[2] + red[3]) * (1.0 / 128.0);
    __syncthreads();
    double var = stat;

    g_ik[l * IHDN + t] = (float)(d * rsqrt(var + 1e-5)) * w[t] + b[t];
}

/* ---------------- rope table (exact trig, computed once) --------------- */
__global__ void rope_table_kernel()
{
    const int l = blockIdx.x;
    const int i = threadIdx.x;
    float sn, cs;
    rope_trig(l, i, &sn, &cs);
    g_rope[l * 32 + i] = make_float2(sn, cs);
}

/* ---------------- rope application (table lookup, l-offset) ------------ */
__global__ void rope_apply_kernel(float* data, int rowStride,
                                  int chunkStride, int off, int nchunks,
                                  int lbase)
{
    const int l = lbase + blockIdx.x;
    const int c = blockIdx.y * blockDim.y + threadIdx.y;
    if (c >= nchunks) return;
    const int i = threadIdx.x;
    float2 sc = g_rope[l * 32 + i];
    float* p = data + (long)l * rowStride + c * chunkStride + off + 2 * i;
    float x1 = p[0], x2 = p[1];
    p[0] = __fsub_rn(__fmul_rn(x1, sc.y), __fmul_rn(x2, sc.x));
    p[1] = __fadd_rn(__fmul_rn(x1, sc.x), __fmul_rn(x2, sc.y));
}

/* ---------------- k_pe = rope(ckv[:,512:576]) -------------------------- */
__global__ void kpe_kernel()
{
    const int l = blockIdx.x;
    const int i = threadIdx.x;
    const float* src = g_ckv + (long)l * (KVLORA + ROPED) + KVLORA + 2 * i;
    float2 sc = g_rope[l * 32 + i];
    float x1 = src[0], x2 = src[1];
    g_kpe[l * ROPED + 2 * i]     = __fsub_rn(__fmul_rn(x1, sc.y), __fmul_rn(x2, sc.x));
    g_kpe[l * ROPED + 2 * i + 1] = __fadd_rn(__fmul_rn(x1, sc.x), __fmul_rn(x2, sc.y));
}

/* ------- indexer: 128(l) x 64(s) tiles, 8x4 microtile, 2 head-groups ---- */
__global__ void __launch_bounds__(256) indexer_kernel(int bl0)
{
    const int bs = blockIdx.x;
    const int bl = bl0 + blockIdx.y;
    const int hz = blockIdx.z;
    const int s0 = bs * 64;
    const int l0 = bl * 128;
    if (s0 > l0 + 127) return;

    __shared__ float iqs[64][128];
    __shared__ float iks[64][64];

    const int tid = threadIdx.x;
    const int tm  = tid >> 4;
    const int tn  = tid & 15;

    float sa[8][4], ca[8][4];
#pragma unroll
    for (int i = 0; i < 8; i++)
#pragma unroll
        for (int j = 0; j < 4; j++) { sa[i][j] = 0.f; ca[i][j] = 0.f; }

    const int qrow = tid >> 1;
    const int qdb  = (tid & 1) * 32;
    const int krow = tid >> 2;
    const int kdb  = (tid & 3) * 16;

    for (int h = hz * 32; h < hz * 32 + 32; h++) {
        float sd[8][4], cd[8][4];
#pragma unroll
        for (int i = 0; i < 8; i++)
#pragma unroll
            for (int j = 0; j < 4; j++) { sd[i][j] = 0.f; cd[i][j] = 0.f; }

        for (int dc = 0; dc < IHDN; dc += 64) {
            __syncthreads();
            {
                const float* src = g_iq + (long)(l0 + qrow) * (IHN * IHDN)
                                   + h * IHDN + dc + qdb;
#pragma unroll
                for (int e = 0; e < 8; e++) {
                    float4 v = *(const float4*)(src + e * 4);
                    iqs[qdb + e * 4 + 0][qrow] = v.x;
                    iqs[qdb + e * 4 + 1][qrow] = v.y;
                    iqs[qdb + e * 4 + 2][qrow] = v.z;
                    iqs[qdb + e * 4 + 3][qrow] = v.w;
                }
                const float* src2 = g_ik + (long)(s0 + krow) * IHDN + dc + kdb;
#pragma unroll
                for (int e = 0; e < 4; e++) {
                    float4 u = *(const float4*)(src2 + e * 4);
                    iks[kdb + e * 4 + 0][krow] = u.x;
                    iks[kdb + e * 4 + 1][krow] = u.y;
                    iks[kdb + e * 4 + 2][krow] = u.z;
                    iks[kdb + e * 4 + 3][krow] = u.w;
                }
            }
            __syncthreads();

#pragma unroll
            for (int g4 = 0; g4 < 4; g4++) {
                float td[8][4];
#pragma unroll
                for (int i = 0; i < 8; i++)
#pragma unroll
                    for (int j = 0; j < 4; j++) td[i][j] = 0.f;

#pragma unroll
                for (int kk = g4 * 16; kk < g4 * 16 + 16; kk++) {
                    float4 va0 = *(const float4*)&iqs[kk][tm << 3];
                    float4 va1 = *(const float4*)&iqs[kk][(tm << 3) + 4];
                    float4 vb  = *(const float4*)&iks[kk][tn << 2];
                    float av[8] = {va0.x, va0.y, va0.z, va0.w,
                                   va1.x, va1.y, va1.z, va1.w};
                    float bv[4] = {vb.x, vb.y, vb.z, vb.w};
#pragma unroll
                    for (int i = 0; i < 8; i++)
#pragma unroll
                        for (int j = 0; j < 4; j++)
                            td[i][j] = __fmaf_rn(av[i], bv[j], td[i][j]);
                }
#pragma unroll
                for (int i = 0; i < 8; i++)
#pragma unroll
                    for (int j = 0; j < 4; j++) {
                        float y = __fsub_rn(td[i][j], cd[i][j]);
                        float u = __fadd_rn(sd[i][j], y);
                        cd[i][j] = __fsub_rn(__fsub_rn(u, sd[i][j]), y);
                        sd[i][j] = u;
                    }
            }
        }

#pragma unroll
        for (int i = 0; i < 8; i++) {
            float wf = __fmul_rn(g_iw[(l0 + (tm << 3) + i) * IHN + h], IW_SCALE);
#pragma unroll
            for (int j = 0; j < 4; j++) {
                float rv = __fmul_rn(fmaxf(sd[i][j], 0.f), wf);
                float y = __fsub_rn(rv, ca[i][j]);
                float u = __fadd_rn(sa[i][j], y);
                ca[i][j] = __fsub_rn(__fsub_rn(u, sa[i][j]), y);
                sa[i][j] = u;
            }
        }
    }

#pragma unroll
    for (int i = 0; i < 8; i++) {
        float4 r;
        r.x = sa[i][0]; r.y = sa[i][1]; r.z = sa[i][2]; r.w = sa[i][3];
        *(float4*)(g_partD + (long)hz * (LSEQ * LSEQ)
                   + (long)(l0 + (tm << 3) + i) * LSEQ + s0 + (tn << 2)) = r;
    }
}

/* --- per-row top-256 on summed indexer planes (bit-exact combine fold) -- */
__global__ void __launch_bounds__(1024) topk_kernel(int lbase)
{
    const int l = lbase + blockIdx.x;
    const int t = threadIdx.x;
    __shared__ float sv[1024];
    __shared__ int   si[1024];

    sv[t] = (t <= l) ? __fadd_rn(g_partD[(long)l * LSEQ + t],
                                 g_partD[(long)LSEQ * LSEQ + (long)l * LSEQ + t])
                     : -INFINITY;
    si[t] = t;
    __syncthreads();

    for (int k = 2; k <= 1024; k <<= 1) {
        for (int j = k >> 1; j > 0; j >>= 1) {
            int p = t ^ j;
            if (p > t) {
                bool desc = ((t & k) == 0);
                float vt = sv[t], vp = sv[p];
                int   it = si[t], ip = si[p];
                bool t_lower = (vt < vp) || (vt == vp && it > ip);
                bool sw = desc ? t_lower : !t_lower;
                if (sw) {
                    sv[t] = vp; sv[p] = vt;
                    si[t] = ip; si[p] = it;
                }
            }
            __syncthreads();
        }
    }
    if (t < NTOPK) g_topk[l * NTOPK + t] = si[t];
}

/* ---- absorbed sparse attention: one block per l, all 32 heads ---------- */
/* phase 1: scores (k/kpe gather, identical arithmetic to prior version);  */
/* warp-local softmax; phase 2: ctx[h] = sum_j p[h,j]*kvlat[sidx[j]] with  */
/* kvlat staged in smem (shared across all heads -> 8x less V traffic).    */
#define ATTN_SMEM ((NH * QHD + NTOPK + NH * NTOPK + 16 * KVLORA) * 4)
__global__ void __launch_bounds__(512) attn_kernel(int lbase)
{
    extern __shared__ float sm_[];
    float* qs   = sm_;                                /* [NH*QHD]    */
    int*   sidx = (int*)(sm_ + NH * QHD);             /* [NTOPK]     */
    float* sc   = sm_ + NH * QHD + NTOPK;             /* [NH][NTOPK] */
    float* kvt  = sc + NH * NTOPK;                    /* [16][512]   */

    const int l    = lbase + blockIdx.x;
    const int tid  = threadIdx.x;
    const int wp   = tid >> 5;
    const int lane = tid & 31;

    for (int idx = tid; idx < NH * QHD; idx += 512) {
        int d = idx % QHD;
        float v = g_q[(long)l * (NH * QHD) + idx];
        qs[idx] = (d >= NOPED) ? v * ATT_SCALE : v;
    }
    if (tid < NTOPK) sidx[tid] = g_topk[l * NTOPK + tid];
    __syncthreads();

    /* phase 1: warp wp computes scores for heads 2wp, 2wp+1 */
#pragma unroll
    for (int e = 0; e < 2; e++) {
        const int h = wp * 2 + e;
        const float* qh = qs + h * QHD;
#pragma unroll 2
        for (int j = 0; j < NTOPK; j++) {
            int s = sidx[j];
            float r = -INFINITY;
            if (s <= l) {
                const float* kp = g_k + ((long)h * LSEQ + s) * NOPED;
                float dn = qh[lane]      * kp[lane]
                         + qh[lane + 32] * kp[lane + 32]
                         + qh[lane + 64] * kp[lane + 64]
                         + qh[lane + 96] * kp[lane + 96];
                const float* pp = g_kpe + s * ROPED;
                float dp = qh[128 + lane] * pp[lane]
                         + qh[160 + lane] * pp[lane + 32];
                float d = dn * ATT_SCALE + dp;
#pragma unroll
                for (int o = 16; o; o >>= 1) d += __shfl_xor_sync(0xffffffffu, d, o);
                r = d;
            }
            if (lane == 0) sc[h * NTOPK + j] = r;
        }
    }
    __syncwarp();

    /* warp-local softmax for the 2 heads */
#pragma unroll
    for (int e = 0; e < 2; e++) {
        const int h = wp * 2 + e;
        float v8[8];
        float m = -INFINITY;
#pragma unroll
        for (int i = 0; i < 8; i++) {
            v8[i] = sc[h * NTOPK + lane + 32 * i];
            m = fmaxf(m, v8[i]);
        }
#pragma unroll
        for (int o = 16; o; o >>= 1) m = fmaxf(m, __shfl_xor_sync(0xffffffffu, m, o));
        float s = 0.f;
#pragma unroll
        for (int i = 0; i < 8; i++) { v8[i] = expf(v8[i] - m); s += v8[i]; }
#pragma unroll
        for (int o = 16; o; o >>= 1) s += __shfl_xor_sync(0xffffffffu, s, o);
        float inv = 1.f / s;
#pragma unroll
        for (int i = 0; i < 8; i++) sc[h * NTOPK + lane + 32 * i] = v8[i] * inv;
    }
    __syncthreads();

    /* phase 2: absorbed context */
    const int hp = tid >> 5;        /* head pair */
    const int cg = tid & 31;
    float ctx0[16], ctx1[16];
#pragma unroll
    for (int i = 0; i < 16; i++) { ctx0[i] = 0.f; ctx1[i] = 0.f; }

    for (int jt = 0; jt < NTOPK; jt += 16) {
        __syncthreads();
        for (int idx = tid; idx < 16 * KVLORA; idx += 512) {
            int ss = idx >> 9, c = idx & (KVLORA - 1);
            kvt[ss * KVLORA + c] = g_kvlat[(long)sidx[jt + ss] * KVLORA + c];
        }
        __syncthreads();
#pragma unroll 4
        for (int ss = 0; ss < 16; ss++) {
            float p0 = sc[(2 * hp) * NTOPK + jt + ss];
            float p1 = sc[(2 * hp + 1) * NTOPK + jt + ss];
            const float* kr = kvt + ss * KVLORA;
#pragma unroll
            for (int i = 0; i < 16; i++) {
                float kv = kr[cg + 32 * i];
                ctx0[i] = __fmaf_rn(p0, kv, ctx0[i]);
                ctx1[i] = __fmaf_rn(p1, kv, ctx1[i]);
            }
        }
    }
#pragma unroll
    for (int i = 0; i < 16; i++) {
        g_ctx[((long)(2 * hp) * LSEQ + l) * KVLORA + cg + 32 * i]     = ctx0[i];
        g_ctx[((long)(2 * hp + 1) * LSEQ + l) * KVLORA + cg + 32 * i] = ctx1[i];
    }
}

/* ---------------------------- launcher --------------------------------- */
extern "C" void kernel_launch(void* const* d_in, const int* in_sizes, int n_in,
                              void* d_out, int out_size)
{
    (void)in_sizes; (void)n_in; (void)out_size;
    const float* x         = (const float*)d_in[0];
    const float* W_qa      = (const float*)d_in[2];
    const float* qa_ln_w   = (const float*)d_in[3];
    const float* W_qb      = (const float*)d_in[4];
    const float* W_kva     = (const float*)d_in[5];
    const float* kva_ln_w  = (const float*)d_in[6];
    const float* W_eq      = (const float*)d_in[7];
    const float* W_uo      = (const float*)d_in[8];
    const float* W_o       = (const float*)d_in[9];
    const float* idx_wqb   = (const float*)d_in[10];
    const float* idx_wk    = (const float*)d_in[11];
    const float* idx_kln_w = (const float*)d_in[12];
    const float* idx_kln_b = (const float*)d_in[13];
    const float* idx_wproj = (const float*)d_in[14];
    float* out = (float*)d_out;

    float *p_qr, *p_q, *p_ckv, *p_kvlat, *p_iq, *p_ik, *p_iw, *p_k, *p_ctx, *p_ao;
    float *p_partA, *p_partB, *p_partC;
    cudaGetSymbolAddress((void**)&p_qr,    g_qr);
    cudaGetSymbolAddress((void**)&p_q,     g_q);
    cudaGetSymbolAddress((void**)&p_ckv,   g_ckv);
    cudaGetSymbolAddress((void**)&p_kvlat, g_kvlat);
    cudaGetSymbolAddress((void**)&p_iq,    g_iq);
    cudaGetSymbolAddress((void**)&p_ik,    g_ik);
    cudaGetSymbolAddress((void**)&p_iw,    g_iw);
    cudaGetSymbolAddress((void**)&p_k,     g_k);
    cudaGetSymbolAddress((void**)&p_ctx,   g_ctx);
    cudaGetSymbolAddress((void**)&p_ao,    g_ao);
    cudaGetSymbolAddress((void**)&p_partA, g_partA);
    cudaGetSymbolAddress((void**)&p_partB, g_partB);
    cudaGetSymbolAddress((void**)&p_partC, g_partC);

    /* 3 streams + 6 events: the R10/R14 configuration that passes teardown */
    static cudaStream_t s1, s2, s3;
    static cudaEvent_t  eRT, eQR, eKV, eIK, eIW, eQ;
    static int init_done = 0;
    if (!init_done) {
        cudaStreamCreateWithFlags(&s1, cudaStreamNonBlocking);
        cudaStreamCreateWithFlags(&s2, cudaStreamNonBlocking);
        cudaStreamCreateWithFlags(&s3, cudaStreamNonBlocking);
        cudaEventCreateWithFlags(&eRT, cudaEventDisableTiming);
        cudaEventCreateWithFlags(&eQR, cudaEventDisableTiming);
        cudaEventCreateWithFlags(&eKV, cudaEventDisableTiming);
        cudaEventCreateWithFlags(&eIK, cudaEventDisableTiming);
        cudaEventCreateWithFlags(&eIW, cudaEventDisableTiming);
        cudaEventCreateWithFlags(&eQ,  cudaEventDisableTiming);
        cudaFuncSetAttribute(attn_kernel,
                             cudaFuncAttributeMaxDynamicSharedMemorySize, ATTN_SMEM);
        init_done = 1;
    }

    /* ---- s0: rope table, then fork ---- */
    rope_table_kernel<<<LSEQ, 32>>>();
    cudaEventRecord(eRT, 0);

    /* ---- s1: kv chain (TC-bound) ---- */
    cudaStreamWaitEvent(s1, eRT, 0);
    gemm_tc<true><<<dim3((KVLORA + ROPED + 127) / 128, LSEQ / 128), 256, 0, s1>>>(
        x, W_kva, p_ckv, LSEQ, KVLORA + ROPED, DMODEL, 0, 0, 0, KVLORA + ROPED, 0);
    rmsnorm_kernel<<<LSEQ, 256, 0, s1>>>(p_ckv, kva_ln_w, p_kvlat, KVLORA, KVLORA + ROPED, KVLORA, 1e-6f);
    kpe_kernel<<<LSEQ, 32, 0, s1>>>();
    gemm_tc<false><<<dim3(NOPED / 128, LSEQ / 128, NH), 256, 0, s1>>>(
        p_kvlat, W_eq, p_k, LSEQ, NOPED, KVLORA,
        0, (long)KVLORA * NOPED, (long)LSEQ * NOPED, NOPED, 0);
    cudaEventRecord(eKV, s1);

    /* ---- s2: ik chain (score-exact Kahan; LN folds the 8-plane combine) ---- */
    cudaStreamWaitEvent(s2, eRT, 0);
    gemm_k128<8><<<dim3(IHDN / 64, LSEQ / 128, 8), 256, 0, s2>>>(x, idx_wk, p_partB, LSEQ, IHDN, DMODEL, 0);
    layernorm_ik_kernel<<<LSEQ, 128, 0, s2>>>(p_partB, (long)LSEQ * IHDN, idx_kln_w, idx_kln_b);
    rope_apply_kernel<<<dim3(LSEQ, 1), dim3(32, 1), 0, s2>>>(p_ik, IHDN, IHDN, 0, 1, 0);
    cudaEventRecord(eIK, s2);

    /* ---- s3: iw chain, then W_qb chain (after qr ready) ---- */
    cudaStreamWaitEvent(s3, eRT, 0);
    gemm_k128<8><<<dim3(IHN / 64, LSEQ / 128, 8), 256, 0, s3>>>(x, idx_wproj, p_partC, LSEQ, IHN, DMODEL, 0);
    combine_kernel<<<(LSEQ * IHN + 255) / 256, 256, 0, s3>>>(p_partC, p_iw, LSEQ * IHN, 8, (long)LSEQ * IHN);
    cudaEventRecord(eIW, s3);

    /* ---- s0: q path (rmsnorm folds the 2-plane combine) ---- */
    gemm_k128<2><<<dim3(QLORA / 64, LSEQ / 128, 2), 256>>>(x, W_qa, p_partA, LSEQ, QLORA, DMODEL, 0);
    rmsnorm_sum2_kernel<<<LSEQ, 256>>>(p_partA, (long)LSEQ * QLORA, qa_ln_w, p_qr, QLORA, 1e-6f);
    cudaEventRecord(eQR, 0);

    /* s3 continues: W_qb -> rope_q (needs qr) */
    cudaStreamWaitEvent(s3, eQR, 0);
    gemm_tc<true><<<dim3(NH * QHD / 128, LSEQ / 128), 256, 0, s3>>>(
        p_qr, W_qb, p_q, LSEQ, NH * QHD, QLORA, 0, 0, 0, NH * QHD, 0);
    rope_apply_kernel<<<dim3(LSEQ, NH / 8), dim3(32, 8), 0, s3>>>(p_q, NH * QHD, QHD, NOPED, NH, 0);
    cudaEventRecord(eQ, s3);

    /* s0 continues: idx_wqb -> rope_iq (critical path) */
    gemm_k128<1><<<dim3(IHN * IHDN / 64, LSEQ / 128, 1), 256>>>(p_qr, idx_wqb, p_iq, LSEQ, IHN * IHDN, QLORA, 0);
    rope_apply_kernel<<<dim3(LSEQ, IHN / 8), dim3(32, 8)>>>(p_iq, IHN * IHDN, IHDN, 0, IHN, 0);

    /* ---- join for indexer; topk folds the 2-plane combine ---- */
    cudaStreamWaitEvent(0, eIK, 0);
    cudaStreamWaitEvent(0, eIW, 0);
    indexer_kernel<<<dim3(LSEQ / 64, LSEQ / 128, 2), 256>>>(0);
    topk_kernel<<<LSEQ, 1024>>>(0);

    /* ---- join for attention (absorbed, per-l block) ---- */
    cudaStreamWaitEvent(0, eKV, 0);
    cudaStreamWaitEvent(0, eQ, 0);
    attn_kernel<<<LSEQ, 512, ATTN_SMEM>>>(0);

    /* ctx @ W_uo^T -> ao (batched over heads, TC) */
    gemm_tc<true><<<dim3(1, LSEQ / 128, NH), 256>>>(
        p_ctx, W_uo, p_ao, LSEQ, VD, KVLORA,
        (long)LSEQ * KVLORA, (long)VD * KVLORA, VD, NH * VD, 0);

    /* output projection (TC) */
    gemm_tc<true><<<dim3(DMODEL / 128, LSEQ / 128), 256>>>(
        p_ao, W_o, out, LSEQ, DMODEL, DMODEL, 0, 0, 0, DMODEL, 0);
}

// round 16
// speedup vs baseline: 1.1389x; 1.1389x over previous
#include <cuda_runtime.h>
#include <math.h>
#include <stdint.h>

#define LSEQ   1024
#define DMODEL 4096
#define NH     32
#define QLORA  1536
#define KVLORA 512
#define ROPED  64
#define NOPED  128
#define VD     128
#define QHD    192
#define IHN    64
#define IHDN   128
#define NTOPK  256

#define ATT_SCALE 0.07216878364870323f   /* 192^-0.5 */
#define IW_SCALE  0.011048543456039806f  /* (64*128)^-0.5 */

__device__ __forceinline__ uint32_t tf32bits(float x)
{
    uint32_t u;
    asm("cvt.rna.tf32.f32 %0, %1;" : "=r"(u) : "f"(x));
    return u;
}

#define MMA8(d, a, b) \
    asm volatile( \
        "mma.sync.aligned.m16n8k8.row.col.f32.tf32.tf32.f32 " \
        "{%0,%1,%2,%3}, {%4,%5,%6,%7}, {%8,%9}, {%0,%1,%2,%3};\n" \
        : "+f"((d)[0]), "+f"((d)[1]), "+f"((d)[2]), "+f"((d)[3]) \
        : "r"((a)[0]), "r"((a)[1]), "r"((a)[2]), "r"((a)[3]), \
          "r"((b)[0]), "r"((b)[1]))

/* Correctly-rounded rope trig: replicate JAX's f32 angle, then exact sincos. */
__device__ __forceinline__ void rope_trig(int l, int i, float* sn, float* cs)
{
    double invd = pow(10000.0, -(double)i * (1.0 / 32.0));
    float  invf = (float)invd;
    float  ang  = (float)l * invf;
    double a    = (double)ang;
    *cs = (float)cos(a);
    *sn = (float)sin(a);
}

/* ---------------- scratch (device globals; no allocs allowed) ------------ */
__device__ float  g_qr   [LSEQ * QLORA];
__device__ float  g_q    [LSEQ * NH * QHD];
__device__ float  g_ckv  [LSEQ * (KVLORA + ROPED)];
__device__ float  g_kvlat[LSEQ * KVLORA];
__device__ float  g_kpe  [LSEQ * ROPED];
__device__ float  g_iq   [LSEQ * IHN * IHDN];
__device__ float  g_ik   [LSEQ * IHDN];
__device__ float  g_iw   [LSEQ * IHN];
__device__ int    g_topk [LSEQ * NTOPK];
__device__ float  g_k    [NH * LSEQ * NOPED];
__device__ float  g_v    [NH * LSEQ * VD];
__device__ float  g_ao   [LSEQ * NH * VD];
__device__ float2 g_rope [LSEQ * 32];
/* separate partial buffers for concurrent producers */
__device__ float  g_partA[2 * LSEQ * QLORA];   /* W_qa K-split partials */
__device__ float  g_partB[8 * LSEQ * IHDN];    /* idx_wk partials */
__device__ float  g_partC[8 * LSEQ * IHN];     /* idx_wproj partials */
__device__ float  g_partD[2 * LSEQ * LSEQ];    /* indexer head-group partials */

/* ================== TF32 tensor-core GEMM (proven R6/R7 version) ========= */
#define TCPAD 4
template <bool TB>
__global__ void __launch_bounds__(256)
gemm_tc(const float* __restrict__ A, const float* __restrict__ B,
        float* __restrict__ C, int M, int N, int K,
        long strideB, long strideC, int m0)
{
    __shared__ uint32_t As[128][32 + TCPAD];
    __shared__ uint32_t Bs[128][32 + TCPAD];

    const float* Bp = B + (long)blockIdx.z * strideB;
    float*       Cp = C + (long)blockIdx.z * strideC;

    const int bm   = m0 + blockIdx.y * 128;
    const int bn   = blockIdx.x * 128;
    const int tid  = threadIdx.x;
    const int wid  = tid >> 5;
    const int lane = tid & 31;
    const int g    = lane >> 2;
    const int t4   = lane & 3;

    const int wm = (wid & 1) * 64;
    const int wn = (wid >> 1) * 32;

    float acc[4][4][4];
#pragma unroll
    for (int mi = 0; mi < 4; mi++)
#pragma unroll
        for (int ni = 0; ni < 4; ni++)
#pragma unroll
            for (int r = 0; r < 4; r++) acc[mi][ni][r] = 0.f;

    const int lr = tid >> 1;
    const int lc = (tid & 1) * 16;

    for (int k0 = 0; k0 < K; k0 += 32) {
#pragma unroll
        for (int q = 0; q < 4; q++) {
            float4 v = *(const float4*)(A + (long)(bm + lr) * K + k0 + lc + q * 4);
            *(uint4*)&As[lr][lc + q * 4] =
                make_uint4(tf32bits(v.x), tf32bits(v.y), tf32bits(v.z), tf32bits(v.w));
        }
        if (TB) {
            int row = bn + lr;
            if (row < N) {
#pragma unroll
                for (int q = 0; q < 4; q++) {
                    float4 v = *(const float4*)(Bp + (long)row * K + k0 + lc + q * 4);
                    *(uint4*)&Bs[lr][lc + q * 4] =
                        make_uint4(tf32bits(v.x), tf32bits(v.y), tf32bits(v.z), tf32bits(v.w));
                }
            } else {
#pragma unroll
                for (int q = 0; q < 4; q++)
                    *(uint4*)&Bs[lr][lc + q * 4] = make_uint4(0, 0, 0, 0);
            }
        } else {
            int k  = tid >> 3;
            int nb = (tid & 7) * 16;
#pragma unroll
            for (int q = 0; q < 16; q += 4) {
                int n = bn + nb + q;
                if (n + 3 < N) {
                    float4 v = *(const float4*)(Bp + (long)(k0 + k) * N + n);
                    Bs[nb + q + 0][k] = tf32bits(v.x);
                    Bs[nb + q + 1][k] = tf32bits(v.y);
                    Bs[nb + q + 2][k] = tf32bits(v.z);
                    Bs[nb + q + 3][k] = tf32bits(v.w);
                } else {
#pragma unroll
                    for (int e = 0; e < 4; e++) {
                        float f = (n + e < N) ? Bp[(long)(k0 + k) * N + n + e] : 0.f;
                        Bs[nb + q + e][k] = tf32bits(f);
                    }
                }
            }
        }
        __syncthreads();

#pragma unroll
        for (int ks = 0; ks < 4; ks++) {
            const int kb = ks * 8;
            uint32_t af[4][4];
#pragma unroll
            for (int mi = 0; mi < 4; mi++) {
                int r = wm + mi * 16;
                af[mi][0] = As[r + g][kb + t4];
                af[mi][1] = As[r + g + 8][kb + t4];
                af[mi][2] = As[r + g][kb + t4 + 4];
                af[mi][3] = As[r + g + 8][kb + t4 + 4];
            }
            uint32_t bf[4][2];
#pragma unroll
            for (int ni = 0; ni < 4; ni++) {
                int c = wn + ni * 8;
                bf[ni][0] = Bs[c + g][kb + t4];
                bf[ni][1] = Bs[c + g][kb + t4 + 4];
            }
#pragma unroll
            for (int mi = 0; mi < 4; mi++)
#pragma unroll
                for (int ni = 0; ni < 4; ni++)
                    MMA8(acc[mi][ni], af[mi], bf[ni]);
        }
        __syncthreads();
    }

#pragma unroll
    for (int mi = 0; mi < 4; mi++) {
#pragma unroll
        for (int ni = 0; ni < 4; ni++) {
            int r0 = bm + wm + mi * 16 + g;
            int c0 = bn + wn + ni * 8 + t4 * 2;
            if (c0 < N) {
                Cp[(long)r0 * N + c0] = acc[mi][ni][0];
                if (c0 + 1 < N) Cp[(long)r0 * N + c0 + 1] = acc[mi][ni][1];
                Cp[(long)(r0 + 8) * N + c0] = acc[mi][ni][2];
                if (c0 + 1 < N) Cp[(long)(r0 + 8) * N + c0 + 1] = acc[mi][ni][3];
            }
        }
    }
}

/* ==== Kahan fp32 GEMM, 32-wide k-tiles + register prefetch ==============
   Numerics BIT-IDENTICAL to the 16-k version: two 16-k FMA blocks per tile,
   Kahan merge after each, same order. Only sync/load structure changed.   */
template <int SPLIT>
__global__ void __launch_bounds__(256)
gemm_k128(const float* __restrict__ A, const float* __restrict__ B,
          float* __restrict__ C, int M, int N, int K, int m0)
{
    __shared__ float As[32][128];
    __shared__ float Bs[32][64];

    const int bm    = m0 + blockIdx.y * 128;
    const int bn    = blockIdx.x * 64;
    const int kLen  = K / SPLIT;
    const int kBase = blockIdx.z * kLen;
    float* Cp = C + (long)blockIdx.z * M * N;

    const int tid = threadIdx.x;
    const int tm  = tid >> 4;
    const int tn  = tid & 15;

    const int ar = tid >> 1;            /* 0..127 */
    const int ac = (tid & 1) * 16;      /* 0 or 16 */
    const int br = tid >> 2;            /* 0..63  */
    const int bc = (tid & 3) * 8;       /* 0,8,16,24 */

    float s_[8][4], c_[8][4];
#pragma unroll
    for (int i = 0; i < 8; i++)
#pragma unroll
        for (int j = 0; j < 4; j++) { s_[i][j] = 0.f; c_[i][j] = 0.f; }

    float4 pa[4], pb[2];

    auto gload = [&](int k0) {
#pragma unroll
        for (int q = 0; q < 4; q++)
            pa[q] = *(const float4*)(A + (long)(bm + ar) * K + k0 + ac + q * 4);
#pragma unroll
        for (int q = 0; q < 2; q++)
            pb[q] = *(const float4*)(B + (long)(bn + br) * K + k0 + bc + q * 4);
    };
    auto sstore = [&]() {
#pragma unroll
        for (int q = 0; q < 4; q++) {
            As[ac + q * 4 + 0][ar] = pa[q].x;
            As[ac + q * 4 + 1][ar] = pa[q].y;
            As[ac + q * 4 + 2][ar] = pa[q].z;
            As[ac + q * 4 + 3][ar] = pa[q].w;
        }
#pragma unroll
        for (int q = 0; q < 2; q++) {
            Bs[bc + q * 4 + 0][br] = pb[q].x;
            Bs[bc + q * 4 + 1][br] = pb[q].y;
            Bs[bc + q * 4 + 2][br] = pb[q].z;
            Bs[bc + q * 4 + 3][br] = pb[q].w;
        }
    };

    gload(kBase);
    sstore();
    __syncthreads();

    const int T = kLen / 32;
    for (int t = 0; t < T; t++) {
        if (t + 1 < T) gload(kBase + (t + 1) * 32);

#pragma unroll
        for (int half = 0; half < 2; half++) {
            float t_[8][4];
#pragma unroll
            for (int i = 0; i < 8; i++)
#pragma unroll
                for (int j = 0; j < 4; j++) t_[i][j] = 0.f;

#pragma unroll
            for (int kk = half * 16; kk < half * 16 + 16; kk++) {
                float4 va0 = *(const float4*)&As[kk][tm << 3];
                float4 va1 = *(const float4*)&As[kk][(tm << 3) + 4];
                float4 vb  = *(const float4*)&Bs[kk][tn << 2];
                float av[8] = {va0.x, va0.y, va0.z, va0.w,
                               va1.x, va1.y, va1.z, va1.w};
                float bv[4] = {vb.x, vb.y, vb.z, vb.w};
#pragma unroll
                for (int i = 0; i < 8; i++)
#pragma unroll
                    for (int j = 0; j < 4; j++)
                        t_[i][j] = __fmaf_rn(av[i], bv[j], t_[i][j]);
            }
#pragma unroll
            for (int i = 0; i < 8; i++)
#pragma unroll
                for (int j = 0; j < 4; j++) {
                    float y = __fsub_rn(t_[i][j], c_[i][j]);
                    float u = __fadd_rn(s_[i][j], y);
                    c_[i][j] = __fsub_rn(__fsub_rn(u, s_[i][j]), y);
                    s_[i][j] = u;
                }
        }
        __syncthreads();
        if (t + 1 < T) sstore();
        __syncthreads();
    }

#pragma unroll
    for (int i = 0; i < 8; i++) {
        float4 r;
        r.x = s_[i][0]; r.y = s_[i][1]; r.z = s_[i][2]; r.w = s_[i][3];
        *(float4*)(Cp + (long)(bm + (tm << 3) + i) * N + bn + (tn << 2)) = r;
    }
}

/* ---------------- combine K-split partials (strided planes) ------------- */
__global__ void combine_kernel(const float* __restrict__ part,
                               float* __restrict__ dst, int count, int S,
                               long stride)
{
    int i = blockIdx.x * 256 + threadIdx.x;
    if (i < count) {
        float s = part[i];
        for (int k = 1; k < S; k++) s = __fadd_rn(s, part[(long)k * stride + i]);
        dst[i] = s;
    }
}

/* ---------------- rmsnorm over a row (double-precision stats) ---------- */
__global__ void rmsnorm_kernel(const float* __restrict__ in,
                               const float* __restrict__ w,
                               float* __restrict__ out,
                               int cols, int inStride, int outStride, float eps)
{
    const int l = blockIdx.x;
    const int t = threadIdx.x;
    __shared__ double red[8];
    __shared__ float rshared;

    double ss = 0.0;
    for (int c = t; c < cols; c += 256) {
        double v = (double)in[(long)l * inStride + c];
        ss += v * v;
    }
#pragma unroll
    for (int o = 16; o; o >>= 1) ss += __shfl_xor_sync(0xffffffffu, ss, o);
    if ((t & 31) == 0) red[t >> 5] = ss;
    __syncthreads();
    if (t == 0) {
        double s = 0.0;
        for (int i = 0; i < 8; i++) s += red[i];
        rshared = (float)rsqrt(s / (double)cols + (double)eps);
    }
    __syncthreads();
    float r = rshared;
    for (int c = t; c < cols; c += 256)
        out[(long)l * outStride + c] = in[(long)l * inStride + c] * r * w[c];
}

/* ------ rmsnorm reading 2 K-split planes (bit-exact combine fold) ------ */
__global__ void rmsnorm_sum2_kernel(const float* __restrict__ part, long plane,
                                    const float* __restrict__ w,
                                    float* __restrict__ out,
                                    int cols, float eps)
{
    const int l = blockIdx.x;
    const int t = threadIdx.x;
    __shared__ double red[8];
    __shared__ float rshared;

    double ss = 0.0;
    for (int c = t; c < cols; c += 256) {
        float v = __fadd_rn(part[(long)l * cols + c], part[plane + (long)l * cols + c]);
        double dv = (double)v;
        ss += dv * dv;
    }
#pragma unroll
    for (int o = 16; o; o >>= 1) ss += __shfl_xor_sync(0xffffffffu, ss, o);
    if ((t & 31) == 0) red[t >> 5] = ss;
    __syncthreads();
    if (t == 0) {
        double s = 0.0;
        for (int i = 0; i < 8; i++) s += red[i];
        rshared = (float)rsqrt(s / (double)cols + (double)eps);
    }
    __syncthreads();
    float r = rshared;
    for (int c = t; c < cols; c += 256) {
        float v = __fadd_rn(part[(long)l * cols + c], part[plane + (long)l * cols + c]);
        out[(long)l * cols + c] = v * r * w[c];
    }
}

/* -------- layernorm on summed idx_wk planes -> g_ik (combine fold) ----- */
__global__ void layernorm_ik_kernel(const float* __restrict__ part, long plane,
                                    const float* __restrict__ w,
                                    const float* __restrict__ b)
{
    const int l = blockIdx.x;
    const int t = threadIdx.x;
    __shared__ double red[4];
    __shared__ double stat;

    float v = part[(long)l * IHDN + t];
#pragma unroll
    for (int k = 1; k < 8; k++)
        v = __fadd_rn(v, part[(long)k * plane + (long)l * IHDN + t]);

    double s = (double)v;
#pragma unroll
    for (int o = 16; o; o >>= 1) s += __shfl_xor_sync(0xffffffffu, s, o);
    if ((t & 31) == 0) red[t >> 5] = s;
    __syncthreads();
    if (t == 0) stat = (red[0] + red[1] + red[2] + red[3]) * (1.0 / 128.0);
    __syncthreads();
    double mu = stat;
    double d  = (double)v - mu;

    double s2 = d * d;
#pragma unroll
    for (int o = 16; o; o >>= 1) s2 += __shfl_xor_sync(0xffffffffu, s2, o);
    __syncthreads();
    if ((t & 31) == 0) red[t >> 5] = s2;
    __syncthreads();
    if (t == 0) stat = (red[0] + red[1] + red[2] + red[3]) * (1.0 / 128.0);
    __syncthreads();
    double var = stat;

    g_ik[l * IHDN + t] = (float)(d * rsqrt(var + 1e-5)) * w[t] + b[t];
}

/* ---------------- rope table (exact trig, computed once) --------------- */
__global__ void rope_table_kernel()
{
    const int l = blockIdx.x;
    const int i = threadIdx.x;
    float sn, cs;
    rope_trig(l, i, &sn, &cs);
    g_rope[l * 32 + i] = make_float2(sn, cs);
}

/* ---------------- rope application (table lookup, l-offset) ------------ */
__global__ void rope_apply_kernel(float* data, int rowStride,
                                  int chunkStride, int off, int nchunks,
                                  int lbase)
{
    const int l = lbase + blockIdx.x;
    const int c = blockIdx.y * blockDim.y + threadIdx.y;
    if (c >= nchunks) return;
    const int i = threadIdx.x;
    float2 sc = g_rope[l * 32 + i];
    float* p = data + (long)l * rowStride + c * chunkStride + off + 2 * i;
    float x1 = p[0], x2 = p[1];
    p[0] = __fsub_rn(__fmul_rn(x1, sc.y), __fmul_rn(x2, sc.x));
    p[1] = __fadd_rn(__fmul_rn(x1, sc.x), __fmul_rn(x2, sc.y));
}

/* ---------------- k_pe = rope(ckv[:,512:576]) -------------------------- */
__global__ void kpe_kernel()
{
    const int l = blockIdx.x;
    const int i = threadIdx.x;
    const float* src = g_ckv + (long)l * (KVLORA + ROPED) + KVLORA + 2 * i;
    float2 sc = g_rope[l * 32 + i];
    float x1 = src[0], x2 = src[1];
    g_kpe[l * ROPED + 2 * i]     = __fsub_rn(__fmul_rn(x1, sc.y), __fmul_rn(x2, sc.x));
    g_kpe[l * ROPED + 2 * i + 1] = __fadd_rn(__fmul_rn(x1, sc.x), __fmul_rn(x2, sc.y));
}

/* ------- indexer: 128(l) x 64(s) tiles, 8x4 microtile, 2 head-groups ---- */
__global__ void __launch_bounds__(256) indexer_kernel(int bl0)
{
    const int bs = blockIdx.x;
    const int bl = bl0 + blockIdx.y;
    const int hz = blockIdx.z;
    const int s0 = bs * 64;
    const int l0 = bl * 128;
    if (s0 > l0 + 127) return;

    __shared__ float iqs[64][128];
    __shared__ float iks[64][64];

    const int tid = threadIdx.x;
    const int tm  = tid >> 4;
    const int tn  = tid & 15;

    float sa[8][4], ca[8][4];
#pragma unroll
    for (int i = 0; i < 8; i++)
#pragma unroll
        for (int j = 0; j < 4; j++) { sa[i][j] = 0.f; ca[i][j] = 0.f; }

    const int qrow = tid >> 1;
    const int qdb  = (tid & 1) * 32;
    const int krow = tid >> 2;
    const int kdb  = (tid & 3) * 16;

    for (int h = hz * 32; h < hz * 32 + 32; h++) {
        float sd[8][4], cd[8][4];
#pragma unroll
        for (int i = 0; i < 8; i++)
#pragma unroll
            for (int j = 0; j < 4; j++) { sd[i][j] = 0.f; cd[i][j] = 0.f; }

        for (int dc = 0; dc < IHDN; dc += 64) {
            __syncthreads();
            {
                const float* src = g_iq + (long)(l0 + qrow) * (IHN * IHDN)
                                   + h * IHDN + dc + qdb;
#pragma unroll
                for (int e = 0; e < 8; e++) {
                    float4 v = *(const float4*)(src + e * 4);
                    iqs[qdb + e * 4 + 0][qrow] = v.x;
                    iqs[qdb + e * 4 + 1][qrow] = v.y;
                    iqs[qdb + e * 4 + 2][qrow] = v.z;
                    iqs[qdb + e * 4 + 3][qrow] = v.w;
                }
                const float* src2 = g_ik + (long)(s0 + krow) * IHDN + dc + kdb;
#pragma unroll
                for (int e = 0; e < 4; e++) {
                    float4 u = *(const float4*)(src2 + e * 4);
                    iks[kdb + e * 4 + 0][krow] = u.x;
                    iks[kdb + e * 4 + 1][krow] = u.y;
                    iks[kdb + e * 4 + 2][krow] = u.z;
                    iks[kdb + e * 4 + 3][krow] = u.w;
                }
            }
            __syncthreads();

#pragma unroll
            for (int g4 = 0; g4 < 4; g4++) {
                float td[8][4];
#pragma unroll
                for (int i = 0; i < 8; i++)
#pragma unroll
                    for (int j = 0; j < 4; j++) td[i][j] = 0.f;

#pragma unroll
                for (int kk = g4 * 16; kk < g4 * 16 + 16; kk++) {
                    float4 va0 = *(const float4*)&iqs[kk][tm << 3];
                    float4 va1 = *(const float4*)&iqs[kk][(tm << 3) + 4];
                    float4 vb  = *(const float4*)&iks[kk][tn << 2];
                    float av[8] = {va0.x, va0.y, va0.z, va0.w,
                                   va1.x, va1.y, va1.z, va1.w};
                    float bv[4] = {vb.x, vb.y, vb.z, vb.w};
#pragma unroll
                    for (int i = 0; i < 8; i++)
#pragma unroll
                        for (int j = 0; j < 4; j++)
                            td[i][j] = __fmaf_rn(av[i], bv[j], td[i][j]);
                }
#pragma unroll
                for (int i = 0; i < 8; i++)
#pragma unroll
                    for (int j = 0; j < 4; j++) {
                        float y = __fsub_rn(td[i][j], cd[i][j]);
                        float u = __fadd_rn(sd[i][j], y);
                        cd[i][j] = __fsub_rn(__fsub_rn(u, sd[i][j]), y);
                        sd[i][j] = u;
                    }
            }
        }

#pragma unroll
        for (int i = 0; i < 8; i++) {
            float wf = __fmul_rn(g_iw[(l0 + (tm << 3) + i) * IHN + h], IW_SCALE);
#pragma unroll
            for (int j = 0; j < 4; j++) {
                float rv = __fmul_rn(fmaxf(sd[i][j], 0.f), wf);
                float y = __fsub_rn(rv, ca[i][j]);
                float u = __fadd_rn(sa[i][j], y);
                ca[i][j] = __fsub_rn(__fsub_rn(u, sa[i][j]), y);
                sa[i][j] = u;
            }
        }
    }

#pragma unroll
    for (int i = 0; i < 8; i++) {
        float4 r;
        r.x = sa[i][0]; r.y = sa[i][1]; r.z = sa[i][2]; r.w = sa[i][3];
        *(float4*)(g_partD + (long)hz * (LSEQ * LSEQ)
                   + (long)(l0 + (tm << 3) + i) * LSEQ + s0 + (tn << 2)) = r;
    }
}

/* --- per-row top-256 on summed indexer planes (bit-exact combine fold) -- */
__global__ void __launch_bounds__(1024) topk_kernel(int lbase)
{
    const int l = lbase + blockIdx.x;
    const int t = threadIdx.x;
    __shared__ float sv[1024];
    __shared__ int   si[1024];

    sv[t] = (t <= l) ? __fadd_rn(g_partD[(long)l * LSEQ + t],
                                 g_partD[(long)LSEQ * LSEQ + (long)l * LSEQ + t])
                     : -INFINITY;
    si[t] = t;
    __syncthreads();

    for (int k = 2; k <= 1024; k <<= 1) {
        for (int j = k >> 1; j > 0; j >>= 1) {
            int p = t ^ j;
            if (p > t) {
                bool desc = ((t & k) == 0);
                float vt = sv[t], vp = sv[p];
                int   it = si[t], ip = si[p];
                bool t_lower = (vt < vp) || (vt == vp && it > ip);
                bool sw = desc ? t_lower : !t_lower;
                if (sw) {
                    sv[t] = vp; sv[p] = vt;
                    si[t] = ip; si[p] = it;
                }
            }
            __syncthreads();
        }
    }
    if (t < NTOPK) g_topk[l * NTOPK + t] = si[t];
}

/* ---------------- sparse attention over selected keys ------------------ */
__global__ void __launch_bounds__(128) attn_kernel(int lbase)
{
    const int l = lbase + blockIdx.x;
    const int h = blockIdx.y;
    const int t = threadIdx.x;
    __shared__ float q[QHD];
    __shared__ int   sidx[NTOPK];
    __shared__ float sc[NTOPK];
    __shared__ float red[4];
    __shared__ float smax, ssum;

    const long qbase = (long)l * (NH * QHD) + h * QHD;
    q[t] = g_q[qbase + t];
    if (t < 64) q[128 + t] = g_q[qbase + 128 + t] * ATT_SCALE;
    sidx[t]       = g_topk[l * NTOPK + t];
    sidx[t + 128] = g_topk[l * NTOPK + t + 128];
    __syncthreads();

    const int warp = t >> 5, lane = t & 31;

    for (int jj = 0; jj < 64; jj++) {
        int j = (warp << 6) + jj;
        int s = sidx[j];
        float r = -INFINITY;
        if (s <= l) {
            const float* kp = g_k + ((long)h * LSEQ + s) * NOPED;
            float dn = q[lane]      * kp[lane]
                     + q[lane + 32] * kp[lane + 32]
                     + q[lane + 64] * kp[lane + 64]
                     + q[lane + 96] * kp[lane + 96];
            const float* pp = g_kpe + s * ROPED;
            float dp = q[128 + lane] * pp[lane]
                     + q[160 + lane] * pp[lane + 32];
            float d = dn * ATT_SCALE + dp;
#pragma unroll
            for (int o = 16; o; o >>= 1) d += __shfl_xor_sync(0xffffffffu, d, o);
            r = d;
        }
        if (lane == 0) sc[j] = r;
    }
    __syncthreads();

    float m = fmaxf(sc[t], sc[t + 128]);
#pragma unroll
    for (int o = 16; o; o >>= 1) m = fmaxf(m, __shfl_xor_sync(0xffffffffu, m, o));
    if (lane == 0) red[warp] = m;
    __syncthreads();
    if (t == 0) smax = fmaxf(fmaxf(red[0], red[1]), fmaxf(red[2], red[3]));
    __syncthreads();
    float mx = smax;

    float p0 = expf(sc[t] - mx);
    float p1 = expf(sc[t + 128] - mx);
    float s = p0 + p1;
#pragma unroll
    for (int o = 16; o; o >>= 1) s += __shfl_xor_sync(0xffffffffu, s, o);
    if (lane == 0) red[warp] = s;
    __syncthreads();
    if (t == 0) ssum = red[0] + red[1] + red[2] + red[3];
    __syncthreads();
    float inv = 1.f / ssum;

    sc[t]       = p0 * inv;
    sc[t + 128] = p1 * inv;
    __syncthreads();

    float acc = 0.f;
    for (int j = 0; j < NTOPK; j++) {
        float p = sc[j];
        if (p != 0.f)
            acc += p * g_v[((long)h * LSEQ + sidx[j]) * VD + t];
    }
    g_ao[(long)l * (NH * VD) + h * VD + t] = acc;
}

/* ---------------------------- launcher --------------------------------- */
extern "C" void kernel_launch(void* const* d_in, const int* in_sizes, int n_in,
                              void* d_out, int out_size)
{
    (void)in_sizes; (void)n_in; (void)out_size;
    const float* x         = (const float*)d_in[0];
    const float* W_qa      = (const float*)d_in[2];
    const float* qa_ln_w   = (const float*)d_in[3];
    const float* W_qb      = (const float*)d_in[4];
    const float* W_kva     = (const float*)d_in[5];
    const float* kva_ln_w  = (const float*)d_in[6];
    const float* W_eq      = (const float*)d_in[7];
    const float* W_uo      = (const float*)d_in[8];
    const float* W_o       = (const float*)d_in[9];
    const float* idx_wqb   = (const float*)d_in[10];
    const float* idx_wk    = (const float*)d_in[11];
    const float* idx_kln_w = (const float*)d_in[12];
    const float* idx_kln_b = (const float*)d_in[13];
    const float* idx_wproj = (const float*)d_in[14];
    float* out = (float*)d_out;

    float *p_qr, *p_q, *p_ckv, *p_kvlat, *p_iq, *p_ik, *p_iw, *p_k, *p_v, *p_ao;
    float *p_partA, *p_partB, *p_partC;
    cudaGetSymbolAddress((void**)&p_qr,    g_qr);
    cudaGetSymbolAddress((void**)&p_q,     g_q);
    cudaGetSymbolAddress((void**)&p_ckv,   g_ckv);
    cudaGetSymbolAddress((void**)&p_kvlat, g_kvlat);
    cudaGetSymbolAddress((void**)&p_iq,    g_iq);
    cudaGetSymbolAddress((void**)&p_ik,    g_ik);
    cudaGetSymbolAddress((void**)&p_iw,    g_iw);
    cudaGetSymbolAddress((void**)&p_k,     g_k);
    cudaGetSymbolAddress((void**)&p_v,     g_v);
    cudaGetSymbolAddress((void**)&p_ao,    g_ao);
    cudaGetSymbolAddress((void**)&p_partA, g_partA);
    cudaGetSymbolAddress((void**)&p_partB, g_partB);
    cudaGetSymbolAddress((void**)&p_partC, g_partC);

    /* 3 streams + 6 events: the R10/R14 configuration that passes teardown */
    static cudaStream_t s1, s2, s3;
    static cudaEvent_t  eRT, eQR, eKV, eIK, eIW, eQ;
    static int init_done = 0;
    if (!init_done) {
        cudaStreamCreateWithFlags(&s1, cudaStreamNonBlocking);
        cudaStreamCreateWithFlags(&s2, cudaStreamNonBlocking);
        cudaStreamCreateWithFlags(&s3, cudaStreamNonBlocking);
        cudaEventCreateWithFlags(&eRT, cudaEventDisableTiming);
        cudaEventCreateWithFlags(&eQR, cudaEventDisableTiming);
        cudaEventCreateWithFlags(&eKV, cudaEventDisableTiming);
        cudaEventCreateWithFlags(&eIK, cudaEventDisableTiming);
        cudaEventCreateWithFlags(&eIW, cudaEventDisableTiming);
        cudaEventCreateWithFlags(&eQ,  cudaEventDisableTiming);
        init_done = 1;
    }

    /* ---- s0: rope table, then fork ---- */
    rope_table_kernel<<<LSEQ, 32>>>();
    cudaEventRecord(eRT, 0);

    /* ---- s1: kv chain (TC-bound) ---- */
    cudaStreamWaitEvent(s1, eRT, 0);
    gemm_tc<true><<<dim3((KVLORA + ROPED + 127) / 128, LSEQ / 128), 256, 0, s1>>>(
        x, W_kva, p_ckv, LSEQ, KVLORA + ROPED, DMODEL, 0, 0, 0);
    rmsnorm_kernel<<<LSEQ, 256, 0, s1>>>(p_ckv, kva_ln_w, p_kvlat, KVLORA, KVLORA + ROPED, KVLORA, 1e-6f);
    kpe_kernel<<<LSEQ, 32, 0, s1>>>();
    gemm_tc<false><<<dim3(NOPED / 128, LSEQ / 128, NH), 256, 0, s1>>>(
        p_kvlat, W_eq, p_k, LSEQ, NOPED, KVLORA, (long)KVLORA * NOPED, (long)LSEQ * NOPED, 0);
    gemm_tc<true><<<dim3(VD / 128, LSEQ / 128, NH), 256, 0, s1>>>(
        p_kvlat, W_uo, p_v, LSEQ, VD, KVLORA, (long)VD * KVLORA, (long)LSEQ * VD, 0);
    cudaEventRecord(eKV, s1);

    /* ---- s2: ik chain (score-exact Kahan; LN folds the 8-plane combine) ---- */
    cudaStreamWaitEvent(s2, eRT, 0);
    gemm_k128<8><<<dim3(IHDN / 64, LSEQ / 128, 8), 256, 0, s2>>>(x, idx_wk, p_partB, LSEQ, IHDN, DMODEL, 0);
    layernorm_ik_kernel<<<LSEQ, 128, 0, s2>>>(p_partB, (long)LSEQ * IHDN, idx_kln_w, idx_kln_b);
    rope_apply_kernel<<<dim3(LSEQ, 1), dim3(32, 1), 0, s2>>>(p_ik, IHDN, IHDN, 0, 1, 0);
    cudaEventRecord(eIK, s2);

    /* ---- s3: iw chain, then W_qb chain (after qr ready) ---- */
    cudaStreamWaitEvent(s3, eRT, 0);
    gemm_k128<8><<<dim3(IHN / 64, LSEQ / 128, 8), 256, 0, s3>>>(x, idx_wproj, p_partC, LSEQ, IHN, DMODEL, 0);
    combine_kernel<<<(LSEQ * IHN + 255) / 256, 256, 0, s3>>>(p_partC, p_iw, LSEQ * IHN, 8, (long)LSEQ * IHN);
    cudaEventRecord(eIW, s3);

    /* ---- s0: q path (rmsnorm folds the 2-plane combine) ---- */
    gemm_k128<2><<<dim3(QLORA / 64, LSEQ / 128, 2), 256>>>(x, W_qa, p_partA, LSEQ, QLORA, DMODEL, 0);
    rmsnorm_sum2_kernel<<<LSEQ, 256>>>(p_partA, (long)LSEQ * QLORA, qa_ln_w, p_qr, QLORA, 1e-6f);
    cudaEventRecord(eQR, 0);

    /* s3 continues: W_qb -> rope_q (needs qr) */
    cudaStreamWaitEvent(s3, eQR, 0);
    gemm_tc<true><<<dim3(NH * QHD / 128, LSEQ / 128), 256, 0, s3>>>(
        p_qr, W_qb, p_q, LSEQ, NH * QHD, QLORA, 0, 0, 0);
    rope_apply_kernel<<<dim3(LSEQ, NH / 8), dim3(32, 8), 0, s3>>>(p_q, NH * QHD, QHD, NOPED, NH, 0);
    cudaEventRecord(eQ, s3);

    /* s0 continues: idx_wqb -> rope_iq (critical path) */
    gemm_k128<1><<<dim3(IHN * IHDN / 64, LSEQ / 128, 1), 256>>>(p_qr, idx_wqb, p_iq, LSEQ, IHN * IHDN, QLORA, 0);
    rope_apply_kernel<<<dim3(LSEQ, IHN / 8), dim3(32, 8)>>>(p_iq, IHN * IHDN, IHDN, 0, IHN, 0);

    /* ---- join for indexer; topk folds the 2-plane combine ---- */
    cudaStreamWaitEvent(0, eIK, 0);
    cudaStreamWaitEvent(0, eIW, 0);
    indexer_kernel<<<dim3(LSEQ / 64, LSEQ / 128, 2), 256>>>(0);
    topk_kernel<<<LSEQ, 1024>>>(0);

    /* ---- join for attention ---- */
    cudaStreamWaitEvent(0, eKV, 0);
    cudaStreamWaitEvent(0, eQ, 0);
    attn_kernel<<<dim3(LSEQ, NH), 128>>>(0);

    /* output projection (TC) */
    gemm_tc<true><<<dim3(DMODEL / 128, LSEQ / 128), 256>>>(p_ao, W_o, out, LSEQ, DMODEL, DMODEL, 0, 0, 0);
}